// round 1
// baseline (speedup 1.0000x reference)
#include <cuda_runtime.h>

#define N_    16
#define CIN_  512
#define COUT_ 512
#define STY_  512
#define H_    64
#define W_    64
#define HW_   (H_*W_)

// Scratch (static __device__ arrays — no allocation allowed)
__device__ float g_s[N_*CIN_];            // style modulation s[n][ci]
__device__ float g_xs[N_*CIN_*HW_];       // premultiplied input (128 MiB)
__device__ float g_wsum2[CIN_*COUT_];     // [ci][co] = sum_k weight^2
__device__ float g_demod[N_*COUT_];       // per-(n,co) demodulation

// ---------------------------------------------------------------------------
// 1) s[n][ci] = style[n] . style_w[ci] + style_b[ci]
// ---------------------------------------------------------------------------
__global__ void style_kernel(const float* __restrict__ style,
                             const float* __restrict__ style_w,
                             const float* __restrict__ style_b) {
    __shared__ float ssty[STY_];
    int n = blockIdx.x;
    int ci = threadIdx.x;
    ssty[ci] = style[n*STY_ + ci];
    __syncthreads();
    const float* wr = style_w + ci*STY_;
    float acc = 0.f;
    #pragma unroll 8
    for (int k = 0; k < STY_; k++) acc += ssty[k] * wr[k];
    g_s[n*CIN_ + ci] = acc + style_b[ci];
}

// ---------------------------------------------------------------------------
// 2) x'[n][ci][y][x] = s[n][ci] * x[n][ci][y][x]   (fold modulation into input)
// ---------------------------------------------------------------------------
__global__ void premul_kernel(const float* __restrict__ x) {
    const int total4 = N_*CIN_*HW_/4;
    for (int i = blockIdx.x*blockDim.x + threadIdx.x; i < total4;
         i += gridDim.x*blockDim.x) {
        float4 v = ((const float4*)x)[i];
        float s = g_s[(i*4)/HW_];   // HW_ divisible by 4 -> same s for all 4
        v.x *= s; v.y *= s; v.z *= s; v.w *= s;
        ((float4*)g_xs)[i] = v;
    }
}

// ---------------------------------------------------------------------------
// 3) wsum2[ci][co] = sum_k weight[co][ci][k]^2
// ---------------------------------------------------------------------------
__global__ void wsum2_kernel(const float* __restrict__ weight) {
    int idx = blockIdx.x*blockDim.x + threadIdx.x;     // co*CIN + ci
    if (idx >= COUT_*CIN_) return;
    int co = idx / CIN_, ci = idx % CIN_;
    const float* w = weight + idx*9;
    float a = 0.f;
    #pragma unroll
    for (int k = 0; k < 9; k++) { float v = w[k]; a += v*v; }
    g_wsum2[ci*COUT_ + co] = a;
}

// ---------------------------------------------------------------------------
// 4) demod[n][co] = rsqrt( sum_ci s[n][ci]^2 * wsum2[ci][co] + eps )
// ---------------------------------------------------------------------------
__global__ void demod_kernel() {
    int t = blockIdx.x*blockDim.x + threadIdx.x;       // n*COUT + co
    int n = t / COUT_, co = t % COUT_;
    float acc = 1e-8f;
    #pragma unroll 4
    for (int ci = 0; ci < CIN_; ci++) {
        float s = g_s[n*CIN_ + ci];                    // warp-uniform -> broadcast
        acc += s*s * g_wsum2[ci*COUT_ + co];           // coalesced
    }
    g_demod[t] = rsqrtf(acc);
}

// ---------------------------------------------------------------------------
// 5) Conv 3x3 (shared weight) + demod scale + noise + LeakyReLU(0.2)
//    Block tile: 64 couts x (4 rows x 64 cols) pixels. CI chunk = 8.
//    Thread tile: 8 couts x 8 pixels (rows 0..3, cols {tx, tx+32}).
// ---------------------------------------------------------------------------
__global__ __launch_bounds__(256)
void conv_kernel(const float* __restrict__ weight,
                 const float* __restrict__ noise,
                 const float* __restrict__ noise_w,
                 float* __restrict__ out) {
    __shared__ float sIn[8][6][66];      // [ci][row(-1..+4)][col(-1..+64)]
    __shared__ float sW[8][9][65];       // [ci][k][co], padded to kill conflicts

    const int ht  = blockIdx.x;          // 16 row-tiles of 4
    const int cob = blockIdx.y;          // 8 cout blocks of 64
    const int n   = blockIdx.z;
    const int y0  = ht * 4;
    const int co0 = cob * 64;
    const int tx  = threadIdx.x;         // 0..31 (pixel columns)
    const int ty  = threadIdx.y;         // 0..7  (cout groups)
    const int tid = ty*32 + tx;

    float acc[8][8];
    #pragma unroll
    for (int j = 0; j < 8; j++)
        #pragma unroll
        for (int m = 0; m < 8; m++) acc[j][m] = 0.f;

    for (int ci0 = 0; ci0 < CIN_; ci0 += 8) {
        __syncthreads();   // previous chunk's compute done before overwrite

        // --- load input tile (with halo, zero-padded at borders) ---
        for (int i = tid; i < 8*6*66; i += 256) {
            int ci  = i / (6*66);
            int rem = i % (6*66);
            int rr  = rem / 66, cc = rem % 66;
            int gy = y0 + rr - 1, gx = cc - 1;
            float v = 0.f;
            if (gy >= 0 && gy < H_ && gx >= 0 && gx < W_)
                v = g_xs[((n*CIN_ + ci0 + ci)*H_ + gy)*W_ + gx];
            sIn[ci][rr][cc] = v;
        }
        // --- load weights: i -> (co, ci, k); contiguous global reads per co ---
        for (int i = tid; i < 64*8*9; i += 256) {
            int co  = i / 72;
            int rem = i % 72;
            int ci  = rem / 9, k = rem % 9;
            sW[ci][k][co] = weight[((size_t)(co0 + co)*CIN_ + ci0 + ci)*9 + k];
        }
        __syncthreads();

        #pragma unroll
        for (int ci = 0; ci < 8; ci++) {
            #pragma unroll
            for (int kh = 0; kh < 3; kh++) {
                #pragma unroll
                for (int kw = 0; kw < 3; kw++) {
                    float wv[8], iv[8];
                    #pragma unroll
                    for (int j = 0; j < 8; j++)
                        wv[j] = sW[ci][kh*3 + kw][ty + 8*j];   // broadcast
                    #pragma unroll
                    for (int m = 0; m < 8; m++) {
                        int r = m >> 1;
                        int c = tx + 32*(m & 1);
                        iv[m] = sIn[ci][r + kh][c + kw];       // stride-1
                    }
                    #pragma unroll
                    for (int j = 0; j < 8; j++)
                        #pragma unroll
                        for (int m = 0; m < 8; m++)
                            acc[j][m] += wv[j]*iv[m];
                }
            }
        }
    }

    // --- epilogue: demod scale, noise injection, LeakyReLU(0.2) ---
    const float nw = noise_w[0];
    #pragma unroll
    for (int j = 0; j < 8; j++) {
        int co = co0 + ty + 8*j;
        float dm = g_demod[n*COUT_ + co];
        #pragma unroll
        for (int m = 0; m < 8; m++) {
            int r = m >> 1;
            int c = tx + 32*(m & 1);
            int y = y0 + r;
            float v = acc[j][m] * dm;
            v += nw * noise[(n*H_ + y)*W_ + c];
            v = (v >= 0.f) ? v : 0.2f*v;
            out[(((size_t)n*COUT_ + co)*H_ + y)*W_ + c] = v;
        }
    }
}

// ---------------------------------------------------------------------------
// Inputs (metadata order): x, style, noise, weight, style_w, style_b, noise_weight
// ---------------------------------------------------------------------------
extern "C" void kernel_launch(void* const* d_in, const int* in_sizes, int n_in,
                              void* d_out, int out_size) {
    const float* x        = (const float*)d_in[0];
    const float* style    = (const float*)d_in[1];
    const float* noise    = (const float*)d_in[2];
    const float* weight   = (const float*)d_in[3];
    const float* style_w  = (const float*)d_in[4];
    const float* style_b  = (const float*)d_in[5];
    const float* noise_w  = (const float*)d_in[6];
    float* out = (float*)d_out;

    style_kernel<<<N_, STY_>>>(style, style_w, style_b);
    premul_kernel<<<8192, 256>>>(x);
    wsum2_kernel<<<(COUT_*CIN_)/256, 256>>>(weight);
    demod_kernel<<<(N_*COUT_)/256, 256>>>();

    dim3 grid(H_/4, COUT_/64, N_);
    dim3 blk(32, 8);
    conv_kernel<<<grid, blk>>>(weight, noise, noise_w, out);
}